// round 1
// baseline (speedup 1.0000x reference)
#include <cuda_runtime.h>
#include <cuda_bf16.h>

// Problem shape (fixed by the dataset)
#define MAXN 50000
#define MAXE 1000000

// Scratch: __device__ globals (no allocation allowed in kernel_launch)
__device__ float g_we[MAXE];       // per-edge weight, later folded with inv_deg[dst]
__device__ float g_deg[MAXN];
__device__ float g_inv_deg[MAXN];
__device__ float g_h[MAXN];
__device__ float g_agg[MAXN];

// ---------------------------------------------------------------------------
// Kernel 0: zero degree accumulator
__global__ void k_zero_deg(int n) {
    int i = blockIdx.x * blockDim.x + threadIdx.x;
    if (i < n) g_deg[i] = 0.0f;
}

// ---------------------------------------------------------------------------
// Kernel 1: per-edge MLP  w_e = relu(edge_attr @ w1 + b1) @ w2 + b2
//           plus degree accumulation (atomic, no-return -> REDG)
__global__ void k_edge_mlp(const float* __restrict__ ea,
                           const int*   __restrict__ dst,
                           const float* __restrict__ w1,
                           const float* __restrict__ b1,
                           const float* __restrict__ w2,
                           const float* __restrict__ b2,
                           int E_) {
    __shared__ float s_w1[192];
    __shared__ float s_b1[64];
    __shared__ float s_w2[64];
    int t = threadIdx.x;
    if (t < 192) s_w1[t] = w1[t];
    if (t < 64) { s_b1[t] = b1[t]; s_w2[t] = w2[t]; }
    __syncthreads();

    int e = blockIdx.x * blockDim.x + t;
    if (e >= E_) return;

    float a0 = ea[3 * e + 0];
    float a1 = ea[3 * e + 1];
    float a2 = ea[3 * e + 2];

    float acc = b2[0];
#pragma unroll 16
    for (int j = 0; j < 64; j++) {
        float hj = fmaf(a0, s_w1[j],
                   fmaf(a1, s_w1[64 + j],
                   fmaf(a2, s_w1[128 + j], s_b1[j])));
        acc = fmaf(fmaxf(hj, 0.0f), s_w2[j], acc);
    }
    g_we[e] = acc;
    atomicAdd(&g_deg[dst[e]], 1.0f);   // no return use -> REDG
}

// ---------------------------------------------------------------------------
// Kernel 2: per-node init: h0 = x[:,2], inv_deg, agg = 0
__global__ void k_node_init(const float* __restrict__ x, int n) {
    int i = blockIdx.x * blockDim.x + threadIdx.x;
    if (i >= n) return;
    g_h[i] = x[5 * i + 2];
    float d = g_deg[i];
    g_inv_deg[i] = (d > 0.0f) ? (1.0f / fmaxf(d, 1.0f)) : 0.0f;
    g_agg[i] = 0.0f;
}

// ---------------------------------------------------------------------------
// Kernel 3: fold inv_deg[dst] into the edge weight (loop-invariant)
__global__ void k_scale_we(const int* __restrict__ dst, int E_) {
    int i = blockIdx.x * blockDim.x + threadIdx.x;
    int e = i * 4;
    if (e + 3 < E_) {
        int4   d = *reinterpret_cast<const int4*>(dst + e);
        float4 w = *reinterpret_cast<float4*>(g_we + e);
        w.x *= __ldg(&g_inv_deg[d.x]);
        w.y *= __ldg(&g_inv_deg[d.y]);
        w.z *= __ldg(&g_inv_deg[d.z]);
        w.w *= __ldg(&g_inv_deg[d.w]);
        *reinterpret_cast<float4*>(g_we + e) = w;
    } else {
        for (; e < E_; e++)
            g_we[e] *= g_inv_deg[dst[e]];
    }
}

// ---------------------------------------------------------------------------
// Kernel 4: scatter  agg[dst] += h[src] * we'  (4 edges / thread)
__global__ void k_scatter(const int* __restrict__ src,
                          const int* __restrict__ dst,
                          int E_) {
    int i = blockIdx.x * blockDim.x + threadIdx.x;
    int e = i * 4;
    if (e + 3 < E_) {
        int4   s = *reinterpret_cast<const int4*>(src + e);
        int4   d = *reinterpret_cast<const int4*>(dst + e);
        float4 w = *reinterpret_cast<const float4*>(g_we + e);
        atomicAdd(&g_agg[d.x], __ldg(&g_h[s.x]) * w.x);
        atomicAdd(&g_agg[d.y], __ldg(&g_h[s.y]) * w.y);
        atomicAdd(&g_agg[d.z], __ldg(&g_h[s.z]) * w.z);
        atomicAdd(&g_agg[d.w], __ldg(&g_h[s.w]) * w.w);
    } else {
        for (; e < E_; e++)
            atomicAdd(&g_agg[dst[e]], __ldg(&g_h[src[e]]) * g_we[e]);
    }
}

// ---------------------------------------------------------------------------
// Kernel 5: update  h = relu(agg + h*root + bias); re-zero agg for next iter
__global__ void k_update(const float* __restrict__ root,
                         const float* __restrict__ bias,
                         float* __restrict__ out,
                         int n, int write_out) {
    int i = blockIdx.x * blockDim.x + threadIdx.x;
    if (i >= n) return;
    float v = fmaxf(fmaf(g_h[i], root[0], g_agg[i] + bias[0]), 0.0f);
    g_h[i] = v;
    g_agg[i] = 0.0f;
    if (write_out) out[i] = v;
}

// ---------------------------------------------------------------------------
extern "C" void kernel_launch(void* const* d_in, const int* in_sizes, int n_in,
                              void* d_out, int out_size) {
    const float* x    = (const float*)d_in[0];   // (N,5)
    const int*   ei   = (const int*)  d_in[1];   // (2,E) row-major: src then dst
    const float* ea   = (const float*)d_in[2];   // (E,3)
    const float* w1   = (const float*)d_in[3];   // (3,64)
    const float* b1   = (const float*)d_in[4];   // (64,)
    const float* w2   = (const float*)d_in[5];   // (64,1)
    const float* b2   = (const float*)d_in[6];   // (1,)
    const float* root = (const float*)d_in[7];   // (1,1)
    const float* bias = (const float*)d_in[8];   // (1,)
    float* out = (float*)d_out;

    const int E_ = in_sizes[1] / 2;
    const int N_ = in_sizes[0] / 5;
    const int* src = ei;
    const int* dst = ei + E_;

    const int T = 256;
    const int gN  = (N_ + T - 1) / T;
    const int gE  = (E_ + T - 1) / T;
    const int gE4 = (E_ / 4 + T) / T;   // covers E/4 threads + tail block

    k_zero_deg<<<gN, T>>>(N_);
    k_edge_mlp<<<gE, T>>>(ea, dst, w1, b1, w2, b2, E_);
    k_node_init<<<gN, T>>>(x, N_);
    k_scale_we<<<gE4, T>>>(dst, E_);

    for (int t = 0; t < 4; t++) {
        k_scatter<<<gE4, T>>>(src, dst, E_);
        k_update<<<gN, T>>>(root, bias, out, N_, (t == 3) ? 1 : 0);
    }
}

// round 2
// speedup vs baseline: 1.0584x; 1.0584x over previous
#include <cuda_runtime.h>
#include <cuda_bf16.h>

#define MAXN 50000
#define MAXE 1000000

// Scratch: __device__ globals (no allocation allowed)
__device__ float g_we[MAXE];
__device__ float g_deg[MAXN];
__device__ float g_inv_deg[MAXN];
__device__ float g_h[MAXN];
__device__ float g_agg[MAXN];

typedef unsigned long long ull;

// ---- Blackwell packed f32x2 helpers ----------------------------------------
__device__ __forceinline__ ull pack2(float lo, float hi) {
    ull r; asm("mov.b64 %0, {%1,%2};" : "=l"(r) : "f"(lo), "f"(hi)); return r;
}
__device__ __forceinline__ void unpack2(ull v, float& lo, float& hi) {
    asm("mov.b64 {%0,%1}, %2;" : "=f"(lo), "=f"(hi) : "l"(v));
}
__device__ __forceinline__ ull fma2(ull a, ull b, ull c) {
    ull d; asm("fma.rn.f32x2 %0, %1, %2, %3;" : "=l"(d) : "l"(a), "l"(b), "l"(c)); return d;
}

// ---------------------------------------------------------------------------
__global__ void k_zero_deg(int n) {
    int i = blockIdx.x * blockDim.x + threadIdx.x;
    if (i < n) g_deg[i] = 0.0f;
}

// ---------------------------------------------------------------------------
// Edge MLP: w_e = relu(edge_attr @ w1 + b1) @ w2 + b2, 4 edges/thread using
// packed fp32x2 FMA. Also accumulates in-degree (REDG).
__global__ void k_edge_mlp(const float* __restrict__ ea,
                           const int*   __restrict__ dst,
                           const float* __restrict__ w1,
                           const float* __restrict__ b1,
                           const float* __restrict__ w2,
                           const float* __restrict__ b2,
                           int E_) {
    __shared__ ull s_w1[192];   // packed {w,w}
    __shared__ ull s_b1[64];
    __shared__ ull s_w2[64];
    int t = threadIdx.x;
    if (t < 192) { float w = w1[t]; s_w1[t] = pack2(w, w); }
    if (t < 64)  { float b = b1[t]; s_b1[t] = pack2(b, b);
                   float w = w2[t]; s_w2[t] = pack2(w, w); }
    __syncthreads();

    int e0 = (blockIdx.x * blockDim.x + t) * 4;
    if (e0 >= E_) return;
    float b2v = b2[0];

    if (e0 + 3 < E_) {
        const float4* p = (const float4*)(ea + 3 * e0);   // 3*e0 mult of 4 -> aligned
        float4 v0 = p[0], v1 = p[1], v2 = p[2];
        // e0:(v0.x,v0.y,v0.z) e1:(v0.w,v1.x,v1.y) e2:(v1.z,v1.w,v2.x) e3:(v2.y,v2.z,v2.w)
        ull pa0 = pack2(v0.x, v0.w), pa1 = pack2(v0.y, v1.x), pa2 = pack2(v0.z, v1.y);
        ull pb0 = pack2(v1.z, v2.y), pb1 = pack2(v1.w, v2.z), pb2 = pack2(v2.x, v2.w);
        ull accA = pack2(b2v, b2v), accB = accA;

#pragma unroll 8
        for (int j = 0; j < 64; j++) {
            ull c0 = s_w1[j], c1 = s_w1[64 + j], c2 = s_w1[128 + j];
            ull bb = s_b1[j], ww = s_w2[j];
            ull hA = fma2(pa2, c2, bb); hA = fma2(pa1, c1, hA); hA = fma2(pa0, c0, hA);
            ull hB = fma2(pb2, c2, bb); hB = fma2(pb1, c1, hB); hB = fma2(pb0, c0, hB);
            float l, h;
            unpack2(hA, l, h); l = fmaxf(l, 0.f); h = fmaxf(h, 0.f);
            accA = fma2(pack2(l, h), ww, accA);
            unpack2(hB, l, h); l = fmaxf(l, 0.f); h = fmaxf(h, 0.f);
            accB = fma2(pack2(l, h), ww, accB);
        }
        float r0, r1, r2, r3;
        unpack2(accA, r0, r1); unpack2(accB, r2, r3);
        *(float4*)(g_we + e0) = make_float4(r0, r1, r2, r3);

        int4 d = *(const int4*)(dst + e0);
        atomicAdd(&g_deg[d.x], 1.0f);
        atomicAdd(&g_deg[d.y], 1.0f);
        atomicAdd(&g_deg[d.z], 1.0f);
        atomicAdd(&g_deg[d.w], 1.0f);
    } else {
        for (int e = e0; e < E_; e++) {
            float a0 = ea[3 * e], a1 = ea[3 * e + 1], a2 = ea[3 * e + 2];
            float acc = b2v;
            for (int j = 0; j < 64; j++) {
                float w0l, w0h, w1l, w1h, w2l, w2h, bl, bh, wl, wh;
                unpack2(s_w1[j], w0l, w0h); unpack2(s_w1[64 + j], w1l, w1h);
                unpack2(s_w1[128 + j], w2l, w2h); unpack2(s_b1[j], bl, bh);
                unpack2(s_w2[j], wl, wh);
                float hj = fmaf(a0, w0l, fmaf(a1, w1l, fmaf(a2, w2l, bl)));
                acc = fmaf(fmaxf(hj, 0.f), wl, acc);
            }
            g_we[e] = acc;
            atomicAdd(&g_deg[dst[e]], 1.0f);
        }
    }
}

// ---------------------------------------------------------------------------
__global__ void k_node_init(const float* __restrict__ x, int n) {
    int i = blockIdx.x * blockDim.x + threadIdx.x;
    if (i >= n) return;
    g_h[i] = x[5 * i + 2];
    float d = g_deg[i];
    g_inv_deg[i] = (d > 0.0f) ? (1.0f / fmaxf(d, 1.0f)) : 0.0f;
    g_agg[i] = 0.0f;
}

// ---------------------------------------------------------------------------
// Scatter: agg[dst] += h[src] * we', 8 edges/thread. On iteration 0 (FOLD) the
// loop-invariant inv_deg[dst] is folded into we and written back.
template <bool FOLD>
__global__ void k_scatter(const int* __restrict__ src,
                          const int* __restrict__ dst,
                          int E_) {
    int i = blockIdx.x * blockDim.x + threadIdx.x;
    int e = i * 8;
    if (e + 7 < E_) {
        int4   s0 = *(const int4*)(src + e);
        int4   s1 = *(const int4*)(src + e + 4);
        int4   d0 = *(const int4*)(dst + e);
        int4   d1 = *(const int4*)(dst + e + 4);
        float4 w0 = *(const float4*)(g_we + e);
        float4 w1 = *(const float4*)(g_we + e + 4);
        if (FOLD) {
            w0.x *= __ldg(&g_inv_deg[d0.x]); w0.y *= __ldg(&g_inv_deg[d0.y]);
            w0.z *= __ldg(&g_inv_deg[d0.z]); w0.w *= __ldg(&g_inv_deg[d0.w]);
            w1.x *= __ldg(&g_inv_deg[d1.x]); w1.y *= __ldg(&g_inv_deg[d1.y]);
            w1.z *= __ldg(&g_inv_deg[d1.z]); w1.w *= __ldg(&g_inv_deg[d1.w]);
            *(float4*)(g_we + e)     = w0;
            *(float4*)(g_we + e + 4) = w1;
        }
        float h0 = __ldg(&g_h[s0.x]), h1 = __ldg(&g_h[s0.y]);
        float h2 = __ldg(&g_h[s0.z]), h3 = __ldg(&g_h[s0.w]);
        float h4 = __ldg(&g_h[s1.x]), h5 = __ldg(&g_h[s1.y]);
        float h6 = __ldg(&g_h[s1.z]), h7 = __ldg(&g_h[s1.w]);
        atomicAdd(&g_agg[d0.x], h0 * w0.x);
        atomicAdd(&g_agg[d0.y], h1 * w0.y);
        atomicAdd(&g_agg[d0.z], h2 * w0.z);
        atomicAdd(&g_agg[d0.w], h3 * w0.w);
        atomicAdd(&g_agg[d1.x], h4 * w1.x);
        atomicAdd(&g_agg[d1.y], h5 * w1.y);
        atomicAdd(&g_agg[d1.z], h6 * w1.z);
        atomicAdd(&g_agg[d1.w], h7 * w1.w);
    } else {
        for (; e < E_; e++) {
            float w = g_we[e];
            if (FOLD) { w *= g_inv_deg[dst[e]]; g_we[e] = w; }
            atomicAdd(&g_agg[dst[e]], g_h[src[e]] * w);
        }
    }
}

// ---------------------------------------------------------------------------
__global__ void k_update(const float* __restrict__ root,
                         const float* __restrict__ bias,
                         float* __restrict__ out,
                         int n, int write_out) {
    int i = blockIdx.x * blockDim.x + threadIdx.x;
    if (i >= n) return;
    float v = fmaxf(fmaf(g_h[i], root[0], g_agg[i] + bias[0]), 0.0f);
    g_h[i] = v;
    g_agg[i] = 0.0f;
    if (write_out) out[i] = v;
}

// ---------------------------------------------------------------------------
extern "C" void kernel_launch(void* const* d_in, const int* in_sizes, int n_in,
                              void* d_out, int out_size) {
    const float* x    = (const float*)d_in[0];
    const int*   ei   = (const int*)  d_in[1];
    const float* ea   = (const float*)d_in[2];
    const float* w1   = (const float*)d_in[3];
    const float* b1   = (const float*)d_in[4];
    const float* w2   = (const float*)d_in[5];
    const float* b2   = (const float*)d_in[6];
    const float* root = (const float*)d_in[7];
    const float* bias = (const float*)d_in[8];
    float* out = (float*)d_out;

    const int E_ = in_sizes[1] / 2;
    const int N_ = in_sizes[0] / 5;
    const int* src = ei;
    const int* dst = ei + E_;

    const int T = 256;
    const int gN  = (N_ + T - 1) / T;
    const int gE4 = (E_ + 4 * T - 1) / (4 * T);   // 4 edges/thread (MLP)
    const int gE8 = (E_ + 8 * T - 1) / (8 * T);   // 8 edges/thread (scatter)

    k_zero_deg<<<gN, T>>>(N_);
    k_edge_mlp<<<gE4, T>>>(ea, dst, w1, b1, w2, b2, E_);
    k_node_init<<<gN, T>>>(x, N_);

    k_scatter<true><<<gE8, T>>>(src, dst, E_);    // folds inv_deg into we
    k_update<<<gN, T>>>(root, bias, out, N_, 0);
    for (int t = 1; t < 4; t++) {
        k_scatter<false><<<gE8, T>>>(src, dst, E_);
        k_update<<<gN, T>>>(root, bias, out, N_, (t == 3) ? 1 : 0);
    }
}

// round 3
// speedup vs baseline: 1.0929x; 1.0326x over previous
#include <cuda_runtime.h>
#include <cuda_bf16.h>

#define MAXN 50000
#define MAXE 1000000

// Scratch: __device__ globals (no allocation allowed)
__device__ float g_we[MAXE];
__device__ float g_deg[MAXN];
__device__ float g_h[MAXN];
__device__ float g_agg[MAXN];

typedef unsigned long long ull;

// ---- Blackwell packed f32x2 helpers ----------------------------------------
__device__ __forceinline__ ull pack2(float lo, float hi) {
    ull r; asm("mov.b64 %0, {%1,%2};" : "=l"(r) : "f"(lo), "f"(hi)); return r;
}
__device__ __forceinline__ void unpack2(ull v, float& lo, float& hi) {
    asm("mov.b64 {%0,%1}, %2;" : "=f"(lo), "=f"(hi) : "l"(v));
}
__device__ __forceinline__ ull fma2(ull a, ull b, ull c) {
    ull d; asm("fma.rn.f32x2 %0, %1, %2, %3;" : "=l"(d) : "l"(a), "l"(b), "l"(c)); return d;
}

// ---------------------------------------------------------------------------
__global__ void k_zero_deg(int n) {
    int i = blockIdx.x * blockDim.x + threadIdx.x;
    if (i < n) g_deg[i] = 0.0f;
}

// ---------------------------------------------------------------------------
// Edge MLP: w_e = relu(edge_attr @ w1 + b1) @ w2 + b2, 4 edges/thread using
// packed fp32x2 FMA. Also accumulates in-degree (REDG).
__global__ void k_edge_mlp(const float* __restrict__ ea,
                           const int*   __restrict__ dst,
                           const float* __restrict__ w1,
                           const float* __restrict__ b1,
                           const float* __restrict__ w2,
                           const float* __restrict__ b2,
                           int E_) {
    __shared__ ull s_w1[192];   // packed {w,w}
    __shared__ ull s_b1[64];
    __shared__ ull s_w2[64];
    int t = threadIdx.x;
    if (t < 192) { float w = w1[t]; s_w1[t] = pack2(w, w); }
    if (t < 64)  { float b = b1[t]; s_b1[t] = pack2(b, b);
                   float w = w2[t]; s_w2[t] = pack2(w, w); }
    __syncthreads();

    int e0 = (blockIdx.x * blockDim.x + t) * 4;
    if (e0 >= E_) return;
    float b2v = b2[0];

    if (e0 + 3 < E_) {
        const float4* p = (const float4*)(ea + 3 * e0);   // 3*e0 multiple of 4 -> aligned
        float4 v0 = p[0], v1 = p[1], v2 = p[2];
        // e0:(v0.x,v0.y,v0.z) e1:(v0.w,v1.x,v1.y) e2:(v1.z,v1.w,v2.x) e3:(v2.y,v2.z,v2.w)
        ull pa0 = pack2(v0.x, v0.w), pa1 = pack2(v0.y, v1.x), pa2 = pack2(v0.z, v1.y);
        ull pb0 = pack2(v1.z, v2.y), pb1 = pack2(v1.w, v2.z), pb2 = pack2(v2.x, v2.w);
        ull accA = pack2(b2v, b2v), accB = accA;

#pragma unroll 8
        for (int j = 0; j < 64; j++) {
            ull c0 = s_w1[j], c1 = s_w1[64 + j], c2 = s_w1[128 + j];
            ull bb = s_b1[j], ww = s_w2[j];
            ull hA = fma2(pa2, c2, bb); hA = fma2(pa1, c1, hA); hA = fma2(pa0, c0, hA);
            ull hB = fma2(pb2, c2, bb); hB = fma2(pb1, c1, hB); hB = fma2(pb0, c0, hB);
            float l, h;
            unpack2(hA, l, h); l = fmaxf(l, 0.f); h = fmaxf(h, 0.f);
            accA = fma2(pack2(l, h), ww, accA);
            unpack2(hB, l, h); l = fmaxf(l, 0.f); h = fmaxf(h, 0.f);
            accB = fma2(pack2(l, h), ww, accB);
        }
        float r0, r1, r2, r3;
        unpack2(accA, r0, r1); unpack2(accB, r2, r3);
        *(float4*)(g_we + e0) = make_float4(r0, r1, r2, r3);

        int4 d = *(const int4*)(dst + e0);
        atomicAdd(&g_deg[d.x], 1.0f);
        atomicAdd(&g_deg[d.y], 1.0f);
        atomicAdd(&g_deg[d.z], 1.0f);
        atomicAdd(&g_deg[d.w], 1.0f);
    } else {
        for (int e = e0; e < E_; e++) {
            float a0 = ea[3 * e], a1 = ea[3 * e + 1], a2 = ea[3 * e + 2];
            float acc = b2v;
            for (int j = 0; j < 64; j++) {
                float w0l, w0h, w1l, w1h, w2l, w2h, bl, bh, wl, wh;
                unpack2(s_w1[j], w0l, w0h); unpack2(s_w1[64 + j], w1l, w1h);
                unpack2(s_w1[128 + j], w2l, w2h); unpack2(s_b1[j], bl, bh);
                unpack2(s_w2[j], wl, wh);
                float hj = fmaf(a0, w0l, fmaf(a1, w1l, fmaf(a2, w2l, bl)));
                acc = fmaf(fmaxf(hj, 0.f), wl, acc);
            }
            g_we[e] = acc;
            atomicAdd(&g_deg[dst[e]], 1.0f);
        }
    }
}

// ---------------------------------------------------------------------------
// Node init: h0 = x[:,2], agg = 0. (inv_deg handled inside k_update)
__global__ void k_node_init(const float* __restrict__ x, int n) {
    int i = blockIdx.x * blockDim.x + threadIdx.x;
    if (i >= n) return;
    g_h[i] = x[5 * i + 2];
    g_agg[i] = 0.0f;
}

// ---------------------------------------------------------------------------
// Scatter: agg[dst] += h[src] * we  (pure; 4 edges/thread for occupancy)
__global__ void k_scatter(const int* __restrict__ src,
                          const int* __restrict__ dst,
                          int E_) {
    int i = blockIdx.x * blockDim.x + threadIdx.x;
    int e = i * 4;
    if (e + 3 < E_) {
        int4   s = *(const int4*)(src + e);
        int4   d = *(const int4*)(dst + e);
        float4 w = *(const float4*)(g_we + e);
        float h0 = __ldg(&g_h[s.x]);
        float h1 = __ldg(&g_h[s.y]);
        float h2 = __ldg(&g_h[s.z]);
        float h3 = __ldg(&g_h[s.w]);
        atomicAdd(&g_agg[d.x], h0 * w.x);
        atomicAdd(&g_agg[d.y], h1 * w.y);
        atomicAdd(&g_agg[d.z], h2 * w.z);
        atomicAdd(&g_agg[d.w], h3 * w.w);
    } else {
        for (; e < E_; e++)
            atomicAdd(&g_agg[dst[e]], __ldg(&g_h[src[e]]) * g_we[e]);
    }
}

// ---------------------------------------------------------------------------
// Update: h = relu(agg * inv_deg + h*root + bias); re-zero agg.
// inv_deg computed on the fly from deg (one RCP per node, free).
__global__ void k_update(const float* __restrict__ root,
                         const float* __restrict__ bias,
                         float* __restrict__ out,
                         int n, int write_out) {
    int i = blockIdx.x * blockDim.x + threadIdx.x;
    if (i >= n) return;
    float d = g_deg[i];
    float inv = (d > 0.0f) ? (1.0f / fmaxf(d, 1.0f)) : 0.0f;
    float v = fmaxf(fmaf(g_agg[i], inv, fmaf(g_h[i], root[0], bias[0])), 0.0f);
    g_h[i] = v;
    g_agg[i] = 0.0f;
    if (write_out) out[i] = v;
}

// ---------------------------------------------------------------------------
extern "C" void kernel_launch(void* const* d_in, const int* in_sizes, int n_in,
                              void* d_out, int out_size) {
    const float* x    = (const float*)d_in[0];
    const int*   ei   = (const int*)  d_in[1];
    const float* ea   = (const float*)d_in[2];
    const float* w1   = (const float*)d_in[3];
    const float* b1   = (const float*)d_in[4];
    const float* w2   = (const float*)d_in[5];
    const float* b2   = (const float*)d_in[6];
    const float* root = (const float*)d_in[7];
    const float* bias = (const float*)d_in[8];
    float* out = (float*)d_out;

    const int E_ = in_sizes[1] / 2;
    const int N_ = in_sizes[0] / 5;
    const int* src = ei;
    const int* dst = ei + E_;

    const int T = 256;
    const int gN  = (N_ + T - 1) / T;
    const int gE4 = (E_ + 4 * T - 1) / (4 * T);   // 4 edges/thread

    k_zero_deg<<<gN, T>>>(N_);
    k_edge_mlp<<<gE4, T>>>(ea, dst, w1, b1, w2, b2, E_);
    k_node_init<<<gN, T>>>(x, N_);

    for (int t = 0; t < 4; t++) {
        k_scatter<<<gE4, T>>>(src, dst, E_);
        k_update<<<gN, T>>>(root, bias, out, N_, (t == 3) ? 1 : 0);
    }
}

// round 5
// speedup vs baseline: 1.1122x; 1.0177x over previous
#include <cuda_runtime.h>
#include <cuda_bf16.h>

#define MAXN 50000
#define MAXE 1000000

// Scratch: __device__ globals (no allocation allowed)
__device__ unsigned int g_packed[MAXE];  // (dst<<16)|src when N<=65535
__device__ float g_we[MAXE];
__device__ float g_deg[MAXN];
__device__ float g_h[MAXN];
__device__ float g_agg[MAXN];

typedef unsigned long long ull;

// ---- Blackwell packed f32x2 helpers ----------------------------------------
__device__ __forceinline__ ull pack2(float lo, float hi) {
    ull r; asm("mov.b64 %0, {%1,%2};" : "=l"(r) : "f"(lo), "f"(hi)); return r;
}
__device__ __forceinline__ void unpack2(ull v, float& lo, float& hi) {
    asm("mov.b64 {%0,%1}, %2;" : "=f"(lo), "=f"(hi) : "l"(v));
}
__device__ __forceinline__ ull fma2(ull a, ull b, ull c) {
    ull d; asm("fma.rn.f32x2 %0, %1, %2, %3;" : "=l"(d) : "l"(a), "l"(b), "l"(c)); return d;
}

// ---- PDL intrinsics ---------------------------------------------------------
// CONTRACT (learned in R4): wait() only orders against the predecessor's
// PRE-trigger memory ops. Therefore: trigger AFTER all writes; wait BEFORE the
// first read of predecessor-written data. Pre-wait work may touch only data
// that no in-flight predecessor writes.
__device__ __forceinline__ void pdl_trigger() {
    asm volatile("griddepcontrol.launch_dependents;");
}
__device__ __forceinline__ void pdl_wait() {
    asm volatile("griddepcontrol.wait;" ::: "memory");
}

// ---------------------------------------------------------------------------
// Pack (src,dst) -> uint32. Plain launch, runs first. 4 edges/thread.
__global__ void k_pack(const int* __restrict__ src,
                       const int* __restrict__ dst, int E_) {
    int i = blockIdx.x * blockDim.x + threadIdx.x;
    int e = i * 4;
    if (e + 3 < E_) {
        int4 s = *(const int4*)(src + e);
        int4 d = *(const int4*)(dst + e);
        uint4 p;
        p.x = (unsigned)s.x | ((unsigned)d.x << 16);
        p.y = (unsigned)s.y | ((unsigned)d.y << 16);
        p.z = (unsigned)s.z | ((unsigned)d.z << 16);
        p.w = (unsigned)s.w | ((unsigned)d.w << 16);
        *(uint4*)(g_packed + e) = p;
    } else {
        for (; e < E_; e++)
            g_packed[e] = (unsigned)src[e] | ((unsigned)dst[e] << 16);
    }
    pdl_trigger();
}

// ---------------------------------------------------------------------------
// Init: deg = 0, agg = 0, h = x[:,2]. Trigger AFTER writes.
__global__ void k_init(const float* __restrict__ x, int n) {
    int i = blockIdx.x * blockDim.x + threadIdx.x;
    if (i < n) {
        g_deg[i] = 0.0f;
        g_agg[i] = 0.0f;
        g_h[i]   = x[5 * i + 2];
    }
    pdl_trigger();
}

// ---------------------------------------------------------------------------
// Edge MLP (grid-stride): we = relu(ea@w1+b1)@w2+b2 computed PRE-wait
// (touches nothing init writes); deg REDG AFTER wait (needs zeroed deg).
// Trigger at very end (consumers read g_we and g_deg).
__global__ void __launch_bounds__(256, 6)
k_edge_mlp(const float* __restrict__ ea,
           const int*   __restrict__ dst,
           const float* __restrict__ w1,
           const float* __restrict__ b1,
           const float* __restrict__ w2,
           const float* __restrict__ b2,
           int E_) {
    __shared__ ull s_w1[192];
    __shared__ ull s_b1[64];
    __shared__ ull s_w2[64];
    int t = threadIdx.x;
    if (t < 192) { float w = w1[t]; s_w1[t] = pack2(w, w); }
    if (t < 64)  { float b = b1[t]; s_b1[t] = pack2(b, b);
                   float w = w2[t]; s_w2[t] = pack2(w, w); }
    __syncthreads();

    const int nth = gridDim.x * blockDim.x;
    const int tid = blockIdx.x * blockDim.x + t;
    const float b2v = b2[0];
    const int ngroups = (E_ + 3) >> 2;

    for (int g = tid; g < ngroups; g += nth) {
        int e0 = g * 4;
        if (e0 + 3 < E_) {
            const float4* p = (const float4*)(ea + 3 * e0);
            float4 v0 = p[0], v1 = p[1], v2 = p[2];
            ull pa0 = pack2(v0.x, v0.w), pa1 = pack2(v0.y, v1.x), pa2 = pack2(v0.z, v1.y);
            ull pb0 = pack2(v1.z, v2.y), pb1 = pack2(v1.w, v2.z), pb2 = pack2(v2.x, v2.w);
            ull accA = pack2(b2v, b2v), accB = accA;
#pragma unroll 8
            for (int j = 0; j < 64; j++) {
                ull c0 = s_w1[j], c1 = s_w1[64 + j], c2 = s_w1[128 + j];
                ull bb = s_b1[j], ww = s_w2[j];
                ull hA = fma2(pa2, c2, bb); hA = fma2(pa1, c1, hA); hA = fma2(pa0, c0, hA);
                ull hB = fma2(pb2, c2, bb); hB = fma2(pb1, c1, hB); hB = fma2(pb0, c0, hB);
                float l, h;
                unpack2(hA, l, h); l = fmaxf(l, 0.f); h = fmaxf(h, 0.f);
                accA = fma2(pack2(l, h), ww, accA);
                unpack2(hB, l, h); l = fmaxf(l, 0.f); h = fmaxf(h, 0.f);
                accB = fma2(pack2(l, h), ww, accB);
            }
            float r0, r1, r2, r3;
            unpack2(accA, r0, r1); unpack2(accB, r2, r3);
            *(float4*)(g_we + e0) = make_float4(r0, r1, r2, r3);
        } else {
            for (int e = e0; e < E_; e++) {
                float a0 = ea[3 * e], a1 = ea[3 * e + 1], a2 = ea[3 * e + 2];
                float acc = b2v;
                for (int j = 0; j < 64; j++) {
                    float w0l, w0h, w1l, w1h, w2l, w2h, bl, bh, wl, wh;
                    unpack2(s_w1[j], w0l, w0h); unpack2(s_w1[64 + j], w1l, w1h);
                    unpack2(s_w1[128 + j], w2l, w2h); unpack2(s_b1[j], bl, bh);
                    unpack2(s_w2[j], wl, wh);
                    float hj = fmaf(a0, w0l, fmaf(a1, w1l, fmaf(a2, w2l, bl)));
                    acc = fmaf(fmaxf(hj, 0.f), wl, acc);
                }
                g_we[e] = acc;
            }
        }
    }

    pdl_wait();   // init's deg zeroing must be visible

    for (int g = tid; g < ngroups; g += nth) {
        int e0 = g * 4;
        if (e0 + 3 < E_) {
            int4 d = *(const int4*)(dst + e0);
            atomicAdd(&g_deg[d.x], 1.0f);
            atomicAdd(&g_deg[d.y], 1.0f);
            atomicAdd(&g_deg[d.z], 1.0f);
            atomicAdd(&g_deg[d.w], 1.0f);
        } else {
            for (int e = e0; e < E_; e++) atomicAdd(&g_deg[dst[e]], 1.0f);
        }
    }
    pdl_trigger();
}

// ---------------------------------------------------------------------------
// Scatter (packed): agg[dst] += h[src] * we. Pre-wait: stream packed + we
// (immutable after MLP, which fully completed before our producer launched).
// Post-wait: gather h (written by predecessor update) + REDG agg.
// Trigger at end (update consumes agg).
__global__ void __launch_bounds__(128, 12)
k_scatter_packed(int E_) {
    int i = blockIdx.x * blockDim.x + threadIdx.x;
    int e = i * 4;
    if (e + 3 < E_) {
        uint4  p = *(const uint4*)(g_packed + e);
        float4 w = *(const float4*)(g_we + e);
        pdl_wait();
        float h0 = __ldg(&g_h[p.x & 0xFFFFu]);
        float h1 = __ldg(&g_h[p.y & 0xFFFFu]);
        float h2 = __ldg(&g_h[p.z & 0xFFFFu]);
        float h3 = __ldg(&g_h[p.w & 0xFFFFu]);
        atomicAdd(&g_agg[p.x >> 16], h0 * w.x);
        atomicAdd(&g_agg[p.y >> 16], h1 * w.y);
        atomicAdd(&g_agg[p.z >> 16], h2 * w.z);
        atomicAdd(&g_agg[p.w >> 16], h3 * w.w);
    } else {
        pdl_wait();
        for (; e < E_; e++) {
            unsigned p = g_packed[e];
            atomicAdd(&g_agg[p >> 16], __ldg(&g_h[p & 0xFFFFu]) * g_we[e]);
        }
    }
    pdl_trigger();
}

// Fallback for N > 65535 (not expected for this dataset)
__global__ void __launch_bounds__(128, 12)
k_scatter_wide(const int* __restrict__ src,
               const int* __restrict__ dst, int E_) {
    int i = blockIdx.x * blockDim.x + threadIdx.x;
    int e = i * 4;
    if (e + 3 < E_) {
        int4   s = *(const int4*)(src + e);
        int4   d = *(const int4*)(dst + e);
        float4 w = *(const float4*)(g_we + e);
        pdl_wait();
        float h0 = __ldg(&g_h[s.x]);
        float h1 = __ldg(&g_h[s.y]);
        float h2 = __ldg(&g_h[s.z]);
        float h3 = __ldg(&g_h[s.w]);
        atomicAdd(&g_agg[d.x], h0 * w.x);
        atomicAdd(&g_agg[d.y], h1 * w.y);
        atomicAdd(&g_agg[d.z], h2 * w.z);
        atomicAdd(&g_agg[d.w], h3 * w.w);
    } else {
        pdl_wait();
        for (; e < E_; e++)
            atomicAdd(&g_agg[dst[e]], __ldg(&g_h[src[e]]) * g_we[e]);
    }
    pdl_trigger();
}

// ---------------------------------------------------------------------------
// Update: h = relu(agg*inv_deg + h*root + bias); agg = 0.
// Pre-wait: deg/root/bias (deg immutable after MLP, fully complete).
// Post-wait: agg (predecessor scatter's atomics) and h.
// Trigger at end (successor scatter gathers h and REDGs agg).
__global__ void k_update(const float* __restrict__ root,
                         const float* __restrict__ bias,
                         float* __restrict__ out,
                         int n, int write_out) {
    int i = blockIdx.x * blockDim.x + threadIdx.x;
    if (i < n) {
        float d   = g_deg[i];
        float r   = root[0];
        float b   = bias[0];
        float inv = (d > 0.0f) ? (1.0f / fmaxf(d, 1.0f)) : 0.0f;
        pdl_wait();
        float v = fmaxf(fmaf(g_agg[i], inv, fmaf(g_h[i], r, b)), 0.0f);
        g_h[i] = v;
        g_agg[i] = 0.0f;
        if (write_out) out[i] = v;
    }
    pdl_trigger();
}

// ---------------------------------------------------------------------------
extern "C" void kernel_launch(void* const* d_in, const int* in_sizes, int n_in,
                              void* d_out, int out_size) {
    const float* x    = (const float*)d_in[0];
    const int*   ei   = (const int*)  d_in[1];
    const float* ea   = (const float*)d_in[2];
    const float* w1   = (const float*)d_in[3];
    const float* b1   = (const float*)d_in[4];
    const float* w2   = (const float*)d_in[5];
    const float* b2   = (const float*)d_in[6];
    const float* root = (const float*)d_in[7];
    const float* bias = (const float*)d_in[8];
    float* out = (float*)d_out;

    const int E_ = in_sizes[1] / 2;
    const int N_ = in_sizes[0] / 5;
    const int* src = ei;
    const int* dst = ei + E_;
    const bool packed_ok = (N_ <= 65535);

    int sms = 148;
    cudaDeviceGetAttribute(&sms, cudaDevAttrMultiProcessorCount, 0);

    cudaLaunchAttribute pdlAttr[1];
    pdlAttr[0].id = cudaLaunchAttributeProgrammaticStreamSerialization;
    pdlAttr[0].val.programmaticStreamSerializationAllowed = 1;

    auto launchPDL = [&](void* fn, dim3 grid, dim3 block, void** args) {
        cudaLaunchConfig_t cfg = {};
        cfg.gridDim  = grid;
        cfg.blockDim = block;
        cfg.stream   = 0;
        cfg.attrs    = pdlAttr;
        cfg.numAttrs = 1;
        cudaLaunchKernelExC(&cfg, fn, args);
    };

    int ngroups = (E_ + 3) / 4;

    // pack (plain launch, chain head)
    if (packed_ok) {
        k_pack<<<(ngroups + 127) / 128, 128>>>(src, dst, E_);
        // init (PDL: launches during pack drain; disjoint data)
        { void* a[] = {(void*)&x, (void*)&N_};
          launchPDL((void*)k_init, dim3((N_ + 127) / 128), dim3(128), a); }
    } else {
        k_init<<<(N_ + 127) / 128, 128>>>(x, N_);
    }

    // MLP
    { void* a[] = {(void*)&ea, (void*)&dst, (void*)&w1, (void*)&b1,
                   (void*)&w2, (void*)&b2, (void*)&E_};
      launchPDL((void*)k_edge_mlp, dim3(sms * 6), dim3(256), a); }

    int sblocks = (ngroups + 127) / 128;
    int ublocks = (N_ + 127) / 128;

    for (int t = 0; t < 4; t++) {
        if (packed_ok) {
            void* a[] = {(void*)&E_};
            launchPDL((void*)k_scatter_packed, dim3(sblocks), dim3(128), a);
        } else {
            void* a[] = {(void*)&src, (void*)&dst, (void*)&E_};
            launchPDL((void*)k_scatter_wide, dim3(sblocks), dim3(128), a);
        }
        int wo = (t == 3) ? 1 : 0;
        void* a[] = {(void*)&root, (void*)&bias, (void*)&out, (void*)&N_, (void*)&wo};
        launchPDL((void*)k_update, dim3(ublocks), dim3(128), a);
    }
}